// round 6
// baseline (speedup 1.0000x reference)
#include <cuda_runtime.h>
#include <math.h>
#include <stdint.h>

#define NB 4096

// Scratch (device globals -- no allocation allowed)
__device__ float g_coef[NB * 8];
__device__ float g_h0[NB * 1024];
__device__ float g_h1[NB * 1024];
// tf32-packed, fragment-paired weights: [K/32][16][N] x uint2 {tf32(k), tf32(k+4)}
__device__ uint32_t g_wp0[(4608 / 2) * 1024 * 2];
__device__ uint32_t g_wp1[(8704 / 2) * 1024 * 2];
__device__ uint32_t g_wp2[(8704 / 2) * 512 * 2];
// coef-scaled, tf32 fragment-paired A: [B][K/2] uint2
__device__ uint2 g_ap0[NB * (4608 / 2)];
__device__ uint2 g_ap1[NB * (8704 / 2)];
__device__ uint2 g_ap2[NB * (8704 / 2)];

__device__ __forceinline__ float elu1(float x) {
    return x > 0.f ? x : expm1f(x);
}

__device__ __forceinline__ uint32_t f2tf(float x) {
    uint32_t r;
    asm("cvt.rna.tf32.f32 %0, %1;" : "=r"(r) : "f"(x));
    return r;
}

__device__ __forceinline__ void cp16(uint32_t smem_addr, const void* gptr) {
    asm volatile("cp.async.cg.shared.global [%0], [%1], 16;\n"
                 :: "r"(smem_addr), "l"(gptr));
}
__device__ __forceinline__ void cp_commit() {
    asm volatile("cp.async.commit_group;\n" ::);
}
__device__ __forceinline__ void cp_wait1() {
    asm volatile("cp.async.wait_group 1;\n" ::);
}

__device__ __forceinline__ void mma_tf32(float& d0, float& d1, float& d2, float& d3,
                                         uint32_t a0, uint32_t a1, uint32_t a2, uint32_t a3,
                                         uint32_t b0, uint32_t b1) {
    asm volatile(
        "mma.sync.aligned.m16n8k8.row.col.f32.tf32.tf32.f32 "
        "{%0,%1,%2,%3}, {%4,%5,%6,%7}, {%8,%9}, {%0,%1,%2,%3};\n"
        : "+f"(d0), "+f"(d1), "+f"(d2), "+f"(d3)
        : "r"(a0), "r"(a1), "r"(a2), "r"(a3), "r"(b0), "r"(b1));
}

// ---------------------------------------------------------------------------
// Weight pack (validated R5): W[k][n] -> pair rows of {tf32(k1), tf32(k1+4)}
// ---------------------------------------------------------------------------
template <int N>
__global__ __launch_bounds__(256) void pack_kernel(
    const float* __restrict__ W, uint32_t* __restrict__ Wp, int total)
{
    int idx = blockIdx.x * 256 + threadIdx.x;
    if (idx >= total) return;
    int n = idx % N;
    int r = idx / N;
    int kt = r >> 4, kp = r & 15;
    int k1 = kt * 32 + (kp >> 2) * 8 + (kp & 3);
    uint2 v;
    v.x = f2tf(W[(size_t)k1 * N + n]);
    v.y = f2tf(W[(size_t)(k1 + 4) * N + n]);
    ((uint2*)Wp)[(size_t)r * N + n] = v;
}

// ---------------------------------------------------------------------------
// A expansion: Ap[b][kt*16+p] = { tf32(coef[b,e]*x[b,i(k1)]),
//                                 tf32(coef[b,e]*x[b,i(k1+4)]) }
// k1 = kt*32 + (p>>2)*8 + (p&3); same rounding points as R5's in-loop path.
// ---------------------------------------------------------------------------
template <int XC>
__global__ __launch_bounds__(256) void expand_kernel(
    const float* __restrict__ z, const float* __restrict__ xp,
    const float* __restrict__ coef, uint2* __restrict__ Ap, int total)
{
    constexpr int IN = 64 + XC;
    constexpr int KH = IN * 8 / 2;      // pairs per batch row
    int idx = blockIdx.x * 256 + threadIdx.x;
    if (idx >= total) return;
    int b = idx / KH;
    int r = idx - b * KH;               // kt*16 + p
    int kt = r >> 4, p = r & 15;
    int k1 = kt * 32 + (p >> 2) * 8 + (p & 3);
    int e = k1 / IN;
    int i = k1 - e * IN;                // i and i+4 stay in the same region
    float cf = coef[b * 8 + e];
    const float* src = (i < 64) ? z + (size_t)b * 64 + i
                                : xp + (size_t)b * XC + (i - 64);
    uint2 v;
    v.x = f2tf(src[0] * cf);
    v.y = f2tf(src[4] * cf);
    Ap[idx] = v;
}

// ---------------------------------------------------------------------------
// Gate MLP (R2/R5 version -- measured fastest)
// ---------------------------------------------------------------------------
__global__ __launch_bounds__(128) void gate_kernel(
    const float* __restrict__ z, const float* __restrict__ c,
    const float* __restrict__ gw1, const float* __restrict__ gb1,
    const float* __restrict__ gw2, const float* __restrict__ gb2,
    const float* __restrict__ gw3, const float* __restrict__ gb3,
    float* __restrict__ coef)
{
    constexpr int R = 8;
    __shared__ float xs[R][576];
    __shared__ float h1s[R][128];
    __shared__ float h2s[R][128];
    __shared__ float lg[R][8];

    const int tid = threadIdx.x;
    const int b0 = blockIdx.x * R;

    for (int idx = tid; idx < R * 576; idx += 128) {
        int r = idx / 576;
        int i = idx - r * 576;
        xs[r][i] = (i < 64) ? z[(b0 + r) * 64 + i] : c[(b0 + r) * 512 + (i - 64)];
    }
    __syncthreads();

    float acc[R];
    {
        float bv = gb1[tid];
#pragma unroll
        for (int r = 0; r < R; r++) acc[r] = bv;
        for (int i = 0; i < 576; i++) {
            float w = gw1[i * 128 + tid];
#pragma unroll
            for (int r = 0; r < R; r++) acc[r] = fmaf(xs[r][i], w, acc[r]);
        }
#pragma unroll
        for (int r = 0; r < R; r++) h1s[r][tid] = elu1(acc[r]);
    }
    __syncthreads();

    {
        float bv = gb2[tid];
#pragma unroll
        for (int r = 0; r < R; r++) acc[r] = bv;
        for (int i = 0; i < 128; i++) {
            float w = gw2[i * 128 + tid];
#pragma unroll
            for (int r = 0; r < R; r++) acc[r] = fmaf(h1s[r][i], w, acc[r]);
        }
#pragma unroll
        for (int r = 0; r < R; r++) h2s[r][tid] = elu1(acc[r]);
    }
    __syncthreads();

    if (tid < 64) {
        int r = tid >> 3, e = tid & 7;
        float s = gb3[e];
        for (int i = 0; i < 128; i++) s = fmaf(h2s[r][i], gw3[i * 8 + e], s);
        lg[r][e] = s;
    }
    __syncthreads();

    if (tid < 64) {
        int r = tid >> 3, e = tid & 7;
        float mx = lg[r][0];
#pragma unroll
        for (int j = 1; j < 8; j++) mx = fmaxf(mx, lg[r][j]);
        float sum = 0.f;
#pragma unroll
        for (int j = 0; j < 8; j++) sum += expf(lg[r][j] - mx);
        coef[(b0 + r) * 8 + e] = expf(lg[r][e] - mx) / sum;
    }
}

// ---------------------------------------------------------------------------
// Mixed layer tf32 GEMM. R5 structure; ONLY delta: A now comes pre-scaled &
// pre-converted from Ap (fragment-pair layout) -> mainloop has zero cvt/fmul,
// A fragment = 2 conflict-free LDS.64 (pair stride 20 == 4 mod 16).
// ---------------------------------------------------------------------------
template <int XC, int N, int BN, bool ELU>
__global__ __launch_bounds__(256, 2) void mixed_tc_kernel(
    const uint2* __restrict__ Ap,
    const uint32_t* __restrict__ Wp,
    const float* __restrict__ bias,
    const float* __restrict__ coef,
    float* __restrict__ out)
{
    constexpr int BM = 128;
    constexpr int BK = 32;
    constexpr int IN = 64 + XC;
    constexpr int K = 8 * IN;
    constexpr int KH = K / 2;       // pairs per batch row
    constexpr int NT = K / BK;
    constexpr int ASTp = 20;        // A pair-row stride; 20 % 16 == 4 -> LDS.64 conflict-free
    constexpr int BNp = BN + 4;     // B pair-row stride; % 16 == 4 -> LDS.64 conflict-free
    constexpr int WN = BN / 2;
    constexpr int NTN = WN / 8;

    extern __shared__ char smraw[];
    uint2* AsP = (uint2*)smraw;                       // 2 * BM * ASTp pairs
    uint32_t* Bp = (uint32_t*)(AsP + 2 * BM * ASTp);  // 2 * 16 * BNp * 2 u32
    float* coefS = (float*)(Bp + 2 * 16 * BNp * 2);   // BM * 9
    float* biasS = coefS + BM * 9;                    // 8 * BN

    const int tid = threadIdx.x;
    const int m0 = blockIdx.y * BM;
    const int n0 = blockIdx.x * BN;
    const int w = tid >> 5, lane = tid & 31;
    const int wm0 = (w & 3) * 32;
    const int wn0 = (w >> 2) * WN;
    const int g8 = lane >> 2;
    const int t4 = lane & 3;

    // --- A staging: pure cp.async of pre-expanded pairs (16 pairs/row) ---
    auto loadA = [&](int kt, int stg) {
        uint2* dst = AsP + stg * BM * ASTp;
        const uint2* src = Ap + (size_t)m0 * KH + kt * 16;
#pragma unroll
        for (int j = 0; j < 4; j++) {
            int idx = j * 256 + tid;
            int row = idx >> 3;
            int ch = idx & 7;       // 16B chunk = 2 pairs
            uint32_t sa = (uint32_t)__cvta_generic_to_shared(dst + row * ASTp + ch * 2);
            cp16(sa, src + (size_t)row * KH + ch * 2);
        }
    };

    // --- B staging: cp.async of pre-converted tf32 pairs (validated R5) ---
    auto cpB = [&](int kt, int stg) {
        uint32_t dbase = (uint32_t)__cvta_generic_to_shared(Bp + stg * 16 * BNp * 2);
        const uint32_t* src = Wp + (size_t)kt * 16 * N * 2 + n0 * 2;
        constexpr int CH = 16 * (BN / 2) / 256;
#pragma unroll
        for (int j = 0; j < CH; j++) {
            int idx = j * 256 + tid;
            int r = idx / (BN / 2);
            int c16 = idx - r * (BN / 2);
            cp16(dbase + (r * BNp * 2 + c16 * 4) * 4, src + (size_t)r * N * 2 + c16 * 4);
        }
    };

    // --- prologue ---
    loadA(0, 0);
    cpB(0, 0);
    cp_commit();

    for (int idx = tid; idx < BM * 8; idx += 256)
        coefS[(idx >> 3) * 9 + (idx & 7)] = coef[(size_t)(m0 + (idx >> 3)) * 8 + (idx & 7)];
    for (int idx = tid; idx < 8 * BN; idx += 256) {
        int e = idx / BN, cn = idx - e * BN;
        biasS[e * BN + cn] = bias[(size_t)e * N + n0 + cn];
    }

    float acc[2][NTN][4];
#pragma unroll
    for (int mt = 0; mt < 2; mt++)
#pragma unroll
        for (int nt = 0; nt < NTN; nt++)
#pragma unroll
            for (int q = 0; q < 4; q++) acc[mt][nt][q] = 0.f;

    int buf = 0;
    for (int kt = 0; kt < NT; kt++) {
        const bool more = (kt + 1 < NT);
        if (more) { loadA(kt + 1, buf ^ 1); cpB(kt + 1, buf ^ 1); }
        cp_commit();
        cp_wait1();
        __syncthreads();

        const uint2* Ab = AsP + buf * BM * ASTp;
        const uint32_t* Bb = Bp + buf * 16 * BNp * 2;

#pragma unroll
        for (int s = 0; s < 4; s++) {
            uint32_t af[2][4];
#pragma unroll
            for (int mt = 0; mt < 2; mt++) {
                const int r0 = wm0 + mt * 16 + g8;
                uint2 q0 = Ab[r0 * ASTp + s * 4 + t4];
                uint2 q1 = Ab[(r0 + 8) * ASTp + s * 4 + t4];
                af[mt][0] = q0.x; af[mt][1] = q1.x; af[mt][2] = q0.y; af[mt][3] = q1.y;
            }
#pragma unroll
            for (int nt = 0; nt < NTN; nt++) {
                const int cn = wn0 + nt * 8 + g8;
                uint2 bp = *(const uint2*)&Bb[(s * 4 + t4) * BNp * 2 + cn * 2];
#pragma unroll
                for (int mt = 0; mt < 2; mt++)
                    mma_tf32(acc[mt][nt][0], acc[mt][nt][1], acc[mt][nt][2], acc[mt][nt][3],
                             af[mt][0], af[mt][1], af[mt][2], af[mt][3], bp.x, bp.y);
            }
        }
        __syncthreads();
        buf ^= 1;
    }

    // --- epilogue: + coef·bias, activation, store ---
#pragma unroll
    for (int mt = 0; mt < 2; mt++) {
#pragma unroll
        for (int half = 0; half < 2; half++) {
            const int rl = wm0 + mt * 16 + g8 + half * 8;
            float cfr[8];
#pragma unroll
            for (int e2 = 0; e2 < 8; e2++) cfr[e2] = coefS[rl * 9 + e2];
            float* orow = out + (size_t)(m0 + rl) * N + n0;
#pragma unroll
            for (int nt = 0; nt < NTN; nt++) {
                const int cl = wn0 + nt * 8 + t4 * 2;
                float v0 = acc[mt][nt][half * 2 + 0];
                float v1 = acc[mt][nt][half * 2 + 1];
#pragma unroll
                for (int e2 = 0; e2 < 8; e2++) {
                    v0 = fmaf(cfr[e2], biasS[e2 * BN + cl], v0);
                    v1 = fmaf(cfr[e2], biasS[e2 * BN + cl + 1], v1);
                }
                if (ELU) { v0 = elu1(v0); v1 = elu1(v1); }
                *(float2*)(orow + cl) = make_float2(v0, v1);
            }
        }
    }
}

// ---------------------------------------------------------------------------

static constexpr int smem_bytes(int BN) {
    return 2 * 128 * 20 * 8 + (2 * 16 * (BN + 4) * 2 + 128 * 9 + 8 * BN) * 4;
}

extern "C" void kernel_launch(void* const* d_in, const int* in_sizes, int n_in,
                              void* d_out, int out_size)
{
    const float* z   = (const float*)d_in[0];
    const float* c   = (const float*)d_in[1];
    const float* w0  = (const float*)d_in[2];
    const float* b0  = (const float*)d_in[3];
    const float* w1  = (const float*)d_in[4];
    const float* b1  = (const float*)d_in[5];
    const float* w2  = (const float*)d_in[6];
    const float* b2  = (const float*)d_in[7];
    const float* gw1 = (const float*)d_in[8];
    const float* gb1 = (const float*)d_in[9];
    const float* gw2 = (const float*)d_in[10];
    const float* gb2 = (const float*)d_in[11];
    const float* gw3 = (const float*)d_in[12];
    const float* gb3 = (const float*)d_in[13];

    float *coef, *h0, *h1;
    uint32_t *wp0, *wp1, *wp2;
    uint2 *ap0, *ap1, *ap2;
    cudaGetSymbolAddress((void**)&coef, g_coef);
    cudaGetSymbolAddress((void**)&h0, g_h0);
    cudaGetSymbolAddress((void**)&h1, g_h1);
    cudaGetSymbolAddress((void**)&wp0, g_wp0);
    cudaGetSymbolAddress((void**)&wp1, g_wp1);
    cudaGetSymbolAddress((void**)&wp2, g_wp2);
    cudaGetSymbolAddress((void**)&ap0, g_ap0);
    cudaGetSymbolAddress((void**)&ap1, g_ap1);
    cudaGetSymbolAddress((void**)&ap2, g_ap2);

    cudaFuncSetAttribute(mixed_tc_kernel<512, 1024, 128, true>,
                         cudaFuncAttributeMaxDynamicSharedMemorySize, smem_bytes(128));
    cudaFuncSetAttribute(mixed_tc_kernel<1024, 1024, 128, true>,
                         cudaFuncAttributeMaxDynamicSharedMemorySize, smem_bytes(128));
    cudaFuncSetAttribute(mixed_tc_kernel<1024, 512, 64, false>,
                         cudaFuncAttributeMaxDynamicSharedMemorySize, smem_bytes(64));

    // pack weights to tf32 pair layout
    {
        int t0 = (4608 / 2) * 1024;
        int t1 = (8704 / 2) * 1024;
        int t2 = (8704 / 2) * 512;
        pack_kernel<1024><<<(t0 + 255) / 256, 256>>>(w0, wp0, t0);
        pack_kernel<1024><<<(t1 + 255) / 256, 256>>>(w1, wp1, t1);
        pack_kernel<512><<<(t2 + 255) / 256, 256>>>(w2, wp2, t2);
    }

    gate_kernel<<<NB / 8, 128>>>(z, c, gw1, gb1, gw2, gb2, gw3, gb3, coef);

    const int ta = NB * (4608 / 2);
    const int tb = NB * (8704 / 2);

    // layer0
    expand_kernel<512><<<(ta + 255) / 256, 256>>>(z, c, coef, ap0, ta);
    mixed_tc_kernel<512, 1024, 128, true>
        <<<dim3(1024 / 128, NB / 128), 256, smem_bytes(128)>>>(ap0, wp0, b0, coef, h0);

    // layer1
    expand_kernel<1024><<<(tb + 255) / 256, 256>>>(z, h0, coef, ap1, tb);
    mixed_tc_kernel<1024, 1024, 128, true>
        <<<dim3(1024 / 128, NB / 128), 256, smem_bytes(128)>>>(ap1, wp1, b1, coef, h1);

    // layer2
    expand_kernel<1024><<<(tb + 255) / 256, 256>>>(z, h1, coef, ap2, tb);
    mixed_tc_kernel<1024, 512, 64, false>
        <<<dim3(512 / 64, NB / 128), 256, smem_bytes(64)>>>(ap2, wp2, b2, coef, (float*)d_out);
}

// round 8
// speedup vs baseline: 1.1262x; 1.1262x over previous
#include <cuda_runtime.h>
#include <math.h>
#include <stdint.h>

#define NB 4096

// Scratch (device globals -- no allocation allowed)
__device__ float g_coef[NB * 8];
__device__ float g_h0[NB * 1024];
__device__ float g_h1[NB * 1024];
// tf32-packed, fragment-paired weights: [K/32][16][N] x uint2 {tf32(k), tf32(k+4)}
__device__ uint32_t g_wp0[(4608 / 2) * 1024 * 2];
__device__ uint32_t g_wp1[(8704 / 2) * 1024 * 2];
__device__ uint32_t g_wp2[(8704 / 2) * 512 * 2];

__device__ __forceinline__ float elu1(float x) {
    return x > 0.f ? x : expm1f(x);
}

__device__ __forceinline__ uint32_t f2tf(float x) {
    uint32_t r;
    asm("cvt.rna.tf32.f32 %0, %1;" : "=r"(r) : "f"(x));
    return r;
}

__device__ __forceinline__ void cp16(uint32_t smem_addr, const void* gptr) {
    asm volatile("cp.async.cg.shared.global [%0], [%1], 16;\n"
                 :: "r"(smem_addr), "l"(gptr));
}
__device__ __forceinline__ void cp_commit() {
    asm volatile("cp.async.commit_group;\n" ::);
}
__device__ __forceinline__ void cp_wait1() {
    asm volatile("cp.async.wait_group 1;\n" ::);
}

__device__ __forceinline__ void mma_tf32(float& d0, float& d1, float& d2, float& d3,
                                         uint32_t a0, uint32_t a1, uint32_t a2, uint32_t a3,
                                         uint32_t b0, uint32_t b1) {
    asm volatile(
        "mma.sync.aligned.m16n8k8.row.col.f32.tf32.tf32.f32 "
        "{%0,%1,%2,%3}, {%4,%5,%6,%7}, {%8,%9}, {%0,%1,%2,%3};\n"
        : "+f"(d0), "+f"(d1), "+f"(d2), "+f"(d3)
        : "r"(a0), "r"(a1), "r"(a2), "r"(a3), "r"(b0), "r"(b1));
}

// ---------------------------------------------------------------------------
// Weight pack (validated R5): W[k][n] -> pair rows of {tf32(k1), tf32(k1+4)}
// ---------------------------------------------------------------------------
template <int N>
__global__ __launch_bounds__(256) void pack_kernel(
    const float* __restrict__ W, uint32_t* __restrict__ Wp, int total)
{
    int idx = blockIdx.x * 256 + threadIdx.x;
    if (idx >= total) return;
    int n = idx % N;
    int r = idx / N;
    int kt = r >> 4, kp = r & 15;
    int k1 = kt * 32 + (kp >> 2) * 8 + (kp & 3);
    uint2 v;
    v.x = f2tf(W[(size_t)k1 * N + n]);
    v.y = f2tf(W[(size_t)(k1 + 4) * N + n]);
    ((uint2*)Wp)[(size_t)r * N + n] = v;
}

// ---------------------------------------------------------------------------
// Gate MLP (R2/R5 version -- measured fastest)
// ---------------------------------------------------------------------------
__global__ __launch_bounds__(128) void gate_kernel(
    const float* __restrict__ z, const float* __restrict__ c,
    const float* __restrict__ gw1, const float* __restrict__ gb1,
    const float* __restrict__ gw2, const float* __restrict__ gb2,
    const float* __restrict__ gw3, const float* __restrict__ gb3,
    float* __restrict__ coef)
{
    constexpr int R = 8;
    __shared__ float xs[R][576];
    __shared__ float h1s[R][128];
    __shared__ float h2s[R][128];
    __shared__ float lg[R][8];

    const int tid = threadIdx.x;
    const int b0 = blockIdx.x * R;

    for (int idx = tid; idx < R * 576; idx += 128) {
        int r = idx / 576;
        int i = idx - r * 576;
        xs[r][i] = (i < 64) ? z[(b0 + r) * 64 + i] : c[(b0 + r) * 512 + (i - 64)];
    }
    __syncthreads();

    float acc[R];
    {
        float bv = gb1[tid];
#pragma unroll
        for (int r = 0; r < R; r++) acc[r] = bv;
        for (int i = 0; i < 576; i++) {
            float w = gw1[i * 128 + tid];
#pragma unroll
            for (int r = 0; r < R; r++) acc[r] = fmaf(xs[r][i], w, acc[r]);
        }
#pragma unroll
        for (int r = 0; r < R; r++) h1s[r][tid] = elu1(acc[r]);
    }
    __syncthreads();

    {
        float bv = gb2[tid];
#pragma unroll
        for (int r = 0; r < R; r++) acc[r] = bv;
        for (int i = 0; i < 128; i++) {
            float w = gw2[i * 128 + tid];
#pragma unroll
            for (int r = 0; r < R; r++) acc[r] = fmaf(h1s[r][i], w, acc[r]);
        }
#pragma unroll
        for (int r = 0; r < R; r++) h2s[r][tid] = elu1(acc[r]);
    }
    __syncthreads();

    if (tid < 64) {
        int r = tid >> 3, e = tid & 7;
        float s = gb3[e];
        for (int i = 0; i < 128; i++) s = fmaf(h2s[r][i], gw3[i * 8 + e], s);
        lg[r][e] = s;
    }
    __syncthreads();

    if (tid < 64) {
        int r = tid >> 3, e = tid & 7;
        float mx = lg[r][0];
#pragma unroll
        for (int j = 1; j < 8; j++) mx = fmaxf(mx, lg[r][j]);
        float sum = 0.f;
#pragma unroll
        for (int j = 0; j < 8; j++) sum += expf(lg[r][j] - mx);
        coef[(b0 + r) * 8 + e] = expf(lg[r][e] - mx) / sum;
    }
}

// ---------------------------------------------------------------------------
// Mixed layer tf32 GEMM -- R5 datapath (cp.async raw A + in-loop cvt/coef,
// pre-packed tf32 B), ONLY delta: 3-stage cp.async ring with a SINGLE
// __syncthreads per k-tile (barrier at iter kt proves compute(kt-1) done in
// all warps, so the load into buffer (kt+2)%3 == (kt-1)%3 is safe).
// ---------------------------------------------------------------------------
template <int XC, int N, int BN, bool ELU>
__global__ __launch_bounds__(256, 2) void mixed_tc_kernel(
    const float* __restrict__ z,
    const float* __restrict__ xp,
    const uint32_t* __restrict__ Wp,
    const float* __restrict__ bias,
    const float* __restrict__ coef,
    float* __restrict__ out)
{
    constexpr int BM = 128;
    constexpr int BK = 32;
    constexpr int IN = 64 + XC;
    constexpr int K = 8 * IN;
    constexpr int NT = K / BK;
    constexpr int NS = 3;           // pipeline stages
    constexpr int AST = BK + 4;     // A row stride (floats), scalar loads conflict-free
    constexpr int BNp = BN + 4;     // B pair-row stride; %16==4 -> LDS.64 conflict-free
    constexpr int WN = BN / 2;
    constexpr int NTN = WN / 8;

    extern __shared__ char smraw[];
    float* As = (float*)smraw;                        // NS * BM * AST floats
    uint32_t* Bp = (uint32_t*)(As + NS * BM * AST);   // NS * 16 * BNp * 2 u32
    float* coefS = (float*)(Bp + NS * 16 * BNp * 2);  // BM * 9
    float* biasS = coefS + BM * 9;                    // 8 * BN

    const int tid = threadIdx.x;
    const int m0 = blockIdx.y * BM;
    const int n0 = blockIdx.x * BN;
    const int w = tid >> 5, lane = tid & 31;
    const int wm0 = (w & 3) * 32;
    const int wn0 = (w >> 2) * WN;
    const int g8 = lane >> 2;
    const int t4 = lane & 3;

    // --- A staging: cp.async raw floats, layout As[m][k] stride AST ---
    auto loadA = [&](int kt, int stg) {
        const int e = (kt * BK) / IN;
        const int i0 = kt * BK - e * IN;
        float* dst = As + stg * BM * AST;
        const float* base;
        int stride;
        if (i0 < 64) { base = z + (size_t)m0 * 64 + i0; stride = 64; }
        else         { base = xp + (size_t)m0 * XC + (i0 - 64); stride = XC; }
#pragma unroll
        for (int j = 0; j < 4; j++) {
            int idx = j * 256 + tid;
            int row = idx >> 3;
            int kc4 = (idx & 7) * 4;
            uint32_t sa = (uint32_t)__cvta_generic_to_shared(dst + row * AST + kc4);
            cp16(sa, base + (size_t)row * stride + kc4);
        }
    };

    // --- B staging: cp.async of pre-converted tf32 pairs ---
    auto cpB = [&](int kt, int stg) {
        uint32_t dbase = (uint32_t)__cvta_generic_to_shared(Bp + stg * 16 * BNp * 2);
        const uint32_t* src = Wp + (size_t)kt * 16 * N * 2 + n0 * 2;
        constexpr int CH = 16 * (BN / 2) / 256;
#pragma unroll
        for (int j = 0; j < CH; j++) {
            int idx = j * 256 + tid;
            int r = idx / (BN / 2);
            int c16 = idx - r * (BN / 2);
            cp16(dbase + (r * BNp * 2 + c16 * 4) * 4, src + (size_t)r * N * 2 + c16 * 4);
        }
    };

    // --- prologue: stages 0 and 1 in flight as separate groups ---
    loadA(0, 0);
    cpB(0, 0);
    cp_commit();
    loadA(1, 1);
    cpB(1, 1);
    cp_commit();

    for (int idx = tid; idx < BM * 8; idx += 256)
        coefS[(idx >> 3) * 9 + (idx & 7)] = coef[(size_t)(m0 + (idx >> 3)) * 8 + (idx & 7)];
    for (int idx = tid; idx < 8 * BN; idx += 256) {
        int e = idx / BN, cn = idx - e * BN;
        biasS[e * BN + cn] = bias[(size_t)e * N + n0 + cn];
    }

    float acc[2][NTN][4];
#pragma unroll
    for (int mt = 0; mt < 2; mt++)
#pragma unroll
        for (int nt = 0; nt < NTN; nt++)
#pragma unroll
            for (int q = 0; q < 4; q++) acc[mt][nt][q] = 0.f;

    int buf = 0;        // stage being computed (kt % NS)
    int nbuf = 2;       // stage being filled  ((kt+2) % NS)
    for (int kt = 0; kt < NT; kt++) {
        cp_wait1();             // stage kt's group complete (kt+1 still flying)
        __syncthreads();        // visibility + all warps done with compute(kt-1)

        const int e = (kt * BK) / IN;
        float cf[4];
#pragma unroll
        for (int q = 0; q < 4; q++)
            cf[q] = coefS[(wm0 + g8 + q * 8) * 9 + e];

        const float* Ab = As + buf * BM * AST;
        const uint32_t* Bb = Bp + buf * 16 * BNp * 2;

#pragma unroll
        for (int s = 0; s < 4; s++) {
            uint32_t af[2][4];
#pragma unroll
            for (int mt = 0; mt < 2; mt++) {
                const int r0 = wm0 + mt * 16 + g8;
                af[mt][0] = f2tf(Ab[r0 * AST + s * 8 + t4] * cf[mt * 2 + 0]);
                af[mt][1] = f2tf(Ab[(r0 + 8) * AST + s * 8 + t4] * cf[mt * 2 + 1]);
                af[mt][2] = f2tf(Ab[r0 * AST + s * 8 + t4 + 4] * cf[mt * 2 + 0]);
                af[mt][3] = f2tf(Ab[(r0 + 8) * AST + s * 8 + t4 + 4] * cf[mt * 2 + 1]);
            }
#pragma unroll
            for (int nt = 0; nt < NTN; nt++) {
                const int cn = wn0 + nt * 8 + g8;
                uint2 bp = *(const uint2*)&Bb[(s * 4 + t4) * BNp * 2 + cn * 2];
#pragma unroll
                for (int mt = 0; mt < 2; mt++)
                    mma_tf32(acc[mt][nt][0], acc[mt][nt][1], acc[mt][nt][2], acc[mt][nt][3],
                             af[mt][0], af[mt][1], af[mt][2], af[mt][3], bp.x, bp.y);
            }
        }

        if (kt + 2 < NT) { loadA(kt + 2, nbuf); cpB(kt + 2, nbuf); }
        cp_commit();            // one group per iteration (possibly empty at tail)

        buf = (buf == NS - 1) ? 0 : buf + 1;
        nbuf = (nbuf == NS - 1) ? 0 : nbuf + 1;
    }

    // --- epilogue: + coef·bias, activation, store ---
#pragma unroll
    for (int mt = 0; mt < 2; mt++) {
#pragma unroll
        for (int half = 0; half < 2; half++) {
            const int rl = wm0 + mt * 16 + g8 + half * 8;
            float cfr[8];
#pragma unroll
            for (int e2 = 0; e2 < 8; e2++) cfr[e2] = coefS[rl * 9 + e2];
            float* orow = out + (size_t)(m0 + rl) * N + n0;
#pragma unroll
            for (int nt = 0; nt < NTN; nt++) {
                const int cl = wn0 + nt * 8 + t4 * 2;
                float v0 = acc[mt][nt][half * 2 + 0];
                float v1 = acc[mt][nt][half * 2 + 1];
#pragma unroll
                for (int e2 = 0; e2 < 8; e2++) {
                    v0 = fmaf(cfr[e2], biasS[e2 * BN + cl], v0);
                    v1 = fmaf(cfr[e2], biasS[e2 * BN + cl + 1], v1);
                }
                if (ELU) { v0 = elu1(v0); v1 = elu1(v1); }
                *(float2*)(orow + cl) = make_float2(v0, v1);
            }
        }
    }
}

// ---------------------------------------------------------------------------

static constexpr int smem_bytes(int BN) {
    return (3 * 128 * 36 + 3 * 16 * (BN + 4) * 2 + 128 * 9 + 8 * BN) * 4;
}

extern "C" void kernel_launch(void* const* d_in, const int* in_sizes, int n_in,
                              void* d_out, int out_size)
{
    const float* z   = (const float*)d_in[0];
    const float* c   = (const float*)d_in[1];
    const float* w0  = (const float*)d_in[2];
    const float* b0  = (const float*)d_in[3];
    const float* w1  = (const float*)d_in[4];
    const float* b1  = (const float*)d_in[5];
    const float* w2  = (const float*)d_in[6];
    const float* b2  = (const float*)d_in[7];
    const float* gw1 = (const float*)d_in[8];
    const float* gb1 = (const float*)d_in[9];
    const float* gw2 = (const float*)d_in[10];
    const float* gb2 = (const float*)d_in[11];
    const float* gw3 = (const float*)d_in[12];
    const float* gb3 = (const float*)d_in[13];

    float *coef, *h0, *h1;
    uint32_t *wp0, *wp1, *wp2;
    cudaGetSymbolAddress((void**)&coef, g_coef);
    cudaGetSymbolAddress((void**)&h0, g_h0);
    cudaGetSymbolAddress((void**)&h1, g_h1);
    cudaGetSymbolAddress((void**)&wp0, g_wp0);
    cudaGetSymbolAddress((void**)&wp1, g_wp1);
    cudaGetSymbolAddress((void**)&wp2, g_wp2);

    cudaFuncSetAttribute(mixed_tc_kernel<512, 1024, 128, true>,
                         cudaFuncAttributeMaxDynamicSharedMemorySize, smem_bytes(128));
    cudaFuncSetAttribute(mixed_tc_kernel<1024, 1024, 128, true>,
                         cudaFuncAttributeMaxDynamicSharedMemorySize, smem_bytes(128));
    cudaFuncSetAttribute(mixed_tc_kernel<1024, 512, 64, false>,
                         cudaFuncAttributeMaxDynamicSharedMemorySize, smem_bytes(64));

    // pack weights to tf32 pair layout
    {
        int t0 = (4608 / 2) * 1024;
        int t1 = (8704 / 2) * 1024;
        int t2 = (8704 / 2) * 512;
        pack_kernel<1024><<<(t0 + 255) / 256, 256>>>(w0, wp0, t0);
        pack_kernel<1024><<<(t1 + 255) / 256, 256>>>(w1, wp1, t1);
        pack_kernel<512><<<(t2 + 255) / 256, 256>>>(w2, wp2, t2);
    }

    gate_kernel<<<NB / 8, 128>>>(z, c, gw1, gb1, gw2, gb2, gw3, gb3, coef);

    // layer0: M=4096, K=4608, N=1024
    mixed_tc_kernel<512, 1024, 128, true>
        <<<dim3(1024 / 128, NB / 128), 256, smem_bytes(128)>>>(z, c, wp0, b0, coef, h0);

    // layer1: M=4096, K=8704, N=1024
    mixed_tc_kernel<1024, 1024, 128, true>
        <<<dim3(1024 / 128, NB / 128), 256, smem_bytes(128)>>>(z, h0, wp1, b1, coef, h1);

    // layer2: M=4096, K=8704, N=512
    mixed_tc_kernel<1024, 512, 64, false>
        <<<dim3(512 / 64, NB / 128), 256, smem_bytes(64)>>>(z, h1, wp2, b2, coef, (float*)d_out);
}

// round 10
// speedup vs baseline: 1.7505x; 1.5543x over previous
#include <cuda_runtime.h>
#include <cuda_fp16.h>
#include <math.h>
#include <stdint.h>

#define NB 4096

// Scratch (device globals -- no allocation allowed)
__device__ float g_coef[NB * 8];
__device__ float g_h0[NB * 1024];
__device__ float g_h1[NB * 1024];
// fp16-packed, fragment-paired weights: [K/32][8][N] x uint2
//   { f16x2(W[k0],W[k0+1]), f16x2(W[k0+8],W[k0+9]) },  k0 = kt*32 + (p>>2)*16 + (p&3)*2
__device__ uint2 g_wp0[4608 / 4 * 1024];
__device__ uint2 g_wp1[8704 / 4 * 1024];
__device__ uint2 g_wp2[8704 / 4 * 512];

__device__ __forceinline__ float elu1(float x) {
    return x > 0.f ? x : expm1f(x);
}

__device__ __forceinline__ uint32_t f2h2(float lo, float hi) {
    __half2 h = __floats2half2_rn(lo, hi);   // .x = lo (low 16 bits), .y = hi
    return *(uint32_t*)&h;
}

__device__ __forceinline__ void cp16(uint32_t smem_addr, const void* gptr) {
    asm volatile("cp.async.cg.shared.global [%0], [%1], 16;\n"
                 :: "r"(smem_addr), "l"(gptr));
}
__device__ __forceinline__ void cp_commit() {
    asm volatile("cp.async.commit_group;\n" ::);
}
__device__ __forceinline__ void cp_wait1() {
    asm volatile("cp.async.wait_group 1;\n" ::);
}

__device__ __forceinline__ void mma_f16(float& d0, float& d1, float& d2, float& d3,
                                        uint32_t a0, uint32_t a1, uint32_t a2, uint32_t a3,
                                        uint32_t b0, uint32_t b1) {
    asm volatile(
        "mma.sync.aligned.m16n8k16.row.col.f32.f16.f16.f32 "
        "{%0,%1,%2,%3}, {%4,%5,%6,%7}, {%8,%9}, {%0,%1,%2,%3};\n"
        : "+f"(d0), "+f"(d1), "+f"(d2), "+f"(d3)
        : "r"(a0), "r"(a1), "r"(a2), "r"(a3), "r"(b0), "r"(b1));
}

// ---------------------------------------------------------------------------
// Weight pack: W[k][n] -> [kt][p][n] uint2 of f16x2 pairs matching the
// m16n8k16 B-fragment: p = s*4 + t4, k0 = kt*32 + s*16 + t4*2.
// ---------------------------------------------------------------------------
template <int N>
__global__ __launch_bounds__(256) void pack_kernel(
    const float* __restrict__ W, uint2* __restrict__ Wp, int total)
{
    int idx = blockIdx.x * 256 + threadIdx.x;   // over (K/32)*8*N
    if (idx >= total) return;
    int n = idx % N;
    int r = idx / N;                 // kt*8 + p
    int kt = r >> 3, p = r & 7;
    int k0 = kt * 32 + (p >> 2) * 16 + (p & 3) * 2;
    uint2 v;
    v.x = f2h2(W[(size_t)k0 * N + n],       W[(size_t)(k0 + 1) * N + n]);
    v.y = f2h2(W[(size_t)(k0 + 8) * N + n], W[(size_t)(k0 + 9) * N + n]);
    Wp[idx] = v;
}

// ---------------------------------------------------------------------------
// Gate MLP (R2/R5/R7 version -- measured fastest)
// ---------------------------------------------------------------------------
__global__ __launch_bounds__(128) void gate_kernel(
    const float* __restrict__ z, const float* __restrict__ c,
    const float* __restrict__ gw1, const float* __restrict__ gb1,
    const float* __restrict__ gw2, const float* __restrict__ gb2,
    const float* __restrict__ gw3, const float* __restrict__ gb3,
    float* __restrict__ coef)
{
    constexpr int R = 8;
    __shared__ float xs[R][576];
    __shared__ float h1s[R][128];
    __shared__ float h2s[R][128];
    __shared__ float lg[R][8];

    const int tid = threadIdx.x;
    const int b0 = blockIdx.x * R;

    for (int idx = tid; idx < R * 576; idx += 128) {
        int r = idx / 576;
        int i = idx - r * 576;
        xs[r][i] = (i < 64) ? z[(b0 + r) * 64 + i] : c[(b0 + r) * 512 + (i - 64)];
    }
    __syncthreads();

    float acc[R];
    {
        float bv = gb1[tid];
#pragma unroll
        for (int r = 0; r < R; r++) acc[r] = bv;
        for (int i = 0; i < 576; i++) {
            float w = gw1[i * 128 + tid];
#pragma unroll
            for (int r = 0; r < R; r++) acc[r] = fmaf(xs[r][i], w, acc[r]);
        }
#pragma unroll
        for (int r = 0; r < R; r++) h1s[r][tid] = elu1(acc[r]);
    }
    __syncthreads();

    {
        float bv = gb2[tid];
#pragma unroll
        for (int r = 0; r < R; r++) acc[r] = bv;
        for (int i = 0; i < 128; i++) {
            float w = gw2[i * 128 + tid];
#pragma unroll
            for (int r = 0; r < R; r++) acc[r] = fmaf(h1s[r][i], w, acc[r]);
        }
#pragma unroll
        for (int r = 0; r < R; r++) h2s[r][tid] = elu1(acc[r]);
    }
    __syncthreads();

    if (tid < 64) {
        int r = tid >> 3, e = tid & 7;
        float s = gb3[e];
        for (int i = 0; i < 128; i++) s = fmaf(h2s[r][i], gw3[i * 8 + e], s);
        lg[r][e] = s;
    }
    __syncthreads();

    if (tid < 64) {
        int r = tid >> 3, e = tid & 7;
        float mx = lg[r][0];
#pragma unroll
        for (int j = 1; j < 8; j++) mx = fmaxf(mx, lg[r][j]);
        float sum = 0.f;
#pragma unroll
        for (int j = 0; j < 8; j++) sum += expf(lg[r][j] - mx);
        coef[(b0 + r) * 8 + e] = expf(lg[r][e] - mx) / sum;
    }
}

// ---------------------------------------------------------------------------
// Mixed layer fp16 tensor-core GEMM (fp32 accumulate). R7 pipeline structure
// (3-stage cp.async ring, single barrier per k-tile); m16n8k16.f16 datapath.
//   A: raw fp32 staged (AST=40: float2 LDS.64 conflict-free per 16-lane
//      phase), in-loop coef-mul + cvt.rn.f16x2.
//   B: pre-packed f16x2 fragment pairs, 1 LDS.64 per fragment.
// R9 fix vs R8: cpB chunk count (stage = 8 rows x BN uint2 = 4*BN 16B chunks,
// BN/2 chunks per row -- R8 loaded only half of each row -> NaN).
// ---------------------------------------------------------------------------
template <int XC, int N, int BN, bool ELU>
__global__ __launch_bounds__(256, 2) void mixed_tc_kernel(
    const float* __restrict__ z,
    const float* __restrict__ xp,
    const uint2* __restrict__ Wp,
    const float* __restrict__ bias,
    const float* __restrict__ coef,
    float* __restrict__ out)
{
    constexpr int BM = 128;
    constexpr int BK = 32;
    constexpr int IN = 64 + XC;
    constexpr int K = 8 * IN;
    constexpr int NT = K / BK;
    constexpr int NS = 3;           // pipeline stages
    constexpr int AST = 40;         // A row stride (floats); AST/2 % 16 == 4 -> LDS.64 ok
    constexpr int BNp = BN + 4;     // B pair-row stride (uint2); % 16 == 4 -> LDS.64 ok
    constexpr int WN = BN / 2;
    constexpr int NTN = WN / 8;

    extern __shared__ char smraw[];
    float* As = (float*)smraw;                     // NS * BM * AST floats
    uint2* Bp = (uint2*)(As + NS * BM * AST);      // NS * 8 * BNp uint2
    float* coefS = (float*)(Bp + NS * 8 * BNp);    // BM * 9
    float* biasS = coefS + BM * 9;                 // 8 * BN

    const int tid = threadIdx.x;
    const int m0 = blockIdx.y * BM;
    const int n0 = blockIdx.x * BN;
    const int w = tid >> 5, lane = tid & 31;
    const int wm0 = (w & 3) * 32;
    const int wn0 = (w >> 2) * WN;
    const int g8 = lane >> 2;
    const int t4 = lane & 3;

    // --- A staging: cp.async raw floats, As[m][k] stride AST ---
    auto loadA = [&](int kt, int stg) {
        const int e = (kt * BK) / IN;
        const int i0 = kt * BK - e * IN;
        float* dst = As + stg * BM * AST;
        const float* base;
        int stride;
        if (i0 < 64) { base = z + (size_t)m0 * 64 + i0; stride = 64; }
        else         { base = xp + (size_t)m0 * XC + (i0 - 64); stride = XC; }
#pragma unroll
        for (int j = 0; j < 4; j++) {
            int idx = j * 256 + tid;
            int row = idx >> 3;
            int kc4 = (idx & 7) * 4;
            uint32_t sa = (uint32_t)__cvta_generic_to_shared(dst + row * AST + kc4);
            cp16(sa, base + (size_t)row * stride + kc4);
        }
    };

    // --- B staging: 8 pair-rows x BN uint2 per stage = 4*BN 16B chunks ---
    auto cpB = [&](int kt, int stg) {
        uint32_t dbase = (uint32_t)__cvta_generic_to_shared(Bp + stg * 8 * BNp);
        const uint2* src = Wp + (size_t)kt * 8 * N + n0;
        constexpr int CPR = BN / 2;              // 16B chunks per row (2 uint2 each)
        constexpr int CHUNKS = 8 * CPR;          // 512 (BN=128) or 256 (BN=64)
#pragma unroll
        for (int j = 0; j < CHUNKS / 256; j++) {
            int idx = j * 256 + tid;
            int r = idx / CPR;
            int c16 = idx - r * CPR;
            cp16(dbase + (r * BNp + c16 * 2) * 8, src + (size_t)r * N + c16 * 2);
        }
    };

    // --- prologue: stages 0 and 1 in flight as separate groups ---
    loadA(0, 0);
    cpB(0, 0);
    cp_commit();
    loadA(1, 1);
    cpB(1, 1);
    cp_commit();

    for (int idx = tid; idx < BM * 8; idx += 256)
        coefS[(idx >> 3) * 9 + (idx & 7)] = coef[(size_t)(m0 + (idx >> 3)) * 8 + (idx & 7)];
    for (int idx = tid; idx < 8 * BN; idx += 256) {
        int e = idx / BN, cn = idx - e * BN;
        biasS[e * BN + cn] = bias[(size_t)e * N + n0 + cn];
    }

    float acc[2][NTN][4];
#pragma unroll
    for (int mt = 0; mt < 2; mt++)
#pragma unroll
        for (int nt = 0; nt < NTN; nt++)
#pragma unroll
            for (int q = 0; q < 4; q++) acc[mt][nt][q] = 0.f;

    int buf = 0;        // stage being computed (kt % NS)
    int nbuf = 2;       // stage being filled  ((kt+2) % NS)
    for (int kt = 0; kt < NT; kt++) {
        cp_wait1();             // stage kt's group complete (kt+1 still flying)
        __syncthreads();        // visibility + all warps done with compute(kt-1)

        const int e = (kt * BK) / IN;
        float cf[4];
#pragma unroll
        for (int q = 0; q < 4; q++)
            cf[q] = coefS[(wm0 + g8 + q * 8) * 9 + e];

        const float* Ab = As + buf * BM * AST;
        const uint2* Bb = Bp + buf * 8 * BNp;

#pragma unroll
        for (int s = 0; s < 2; s++) {           // two k16 steps per BK=32
            uint32_t af[2][4];
#pragma unroll
            for (int mt = 0; mt < 2; mt++) {
                const int r0 = wm0 + mt * 16 + g8;
                const float c0 = cf[mt * 2 + 0], c1 = cf[mt * 2 + 1];
                float2 p0 = *(const float2*)&Ab[r0 * AST + s * 16 + t4 * 2];
                float2 p1 = *(const float2*)&Ab[(r0 + 8) * AST + s * 16 + t4 * 2];
                float2 p2 = *(const float2*)&Ab[r0 * AST + s * 16 + t4 * 2 + 8];
                float2 p3 = *(const float2*)&Ab[(r0 + 8) * AST + s * 16 + t4 * 2 + 8];
                af[mt][0] = f2h2(p0.x * c0, p0.y * c0);
                af[mt][1] = f2h2(p1.x * c1, p1.y * c1);
                af[mt][2] = f2h2(p2.x * c0, p2.y * c0);
                af[mt][3] = f2h2(p3.x * c1, p3.y * c1);
            }
#pragma unroll
            for (int nt = 0; nt < NTN; nt++) {
                const int cn = wn0 + nt * 8 + g8;
                uint2 bp = Bb[(s * 4 + t4) * BNp + cn];
#pragma unroll
                for (int mt = 0; mt < 2; mt++)
                    mma_f16(acc[mt][nt][0], acc[mt][nt][1], acc[mt][nt][2], acc[mt][nt][3],
                            af[mt][0], af[mt][1], af[mt][2], af[mt][3], bp.x, bp.y);
            }
        }

        if (kt + 2 < NT) { loadA(kt + 2, nbuf); cpB(kt + 2, nbuf); }
        cp_commit();            // one group per iteration (possibly empty at tail)

        buf = (buf == NS - 1) ? 0 : buf + 1;
        nbuf = (nbuf == NS - 1) ? 0 : nbuf + 1;
    }

    // --- epilogue: + coef·bias, activation, store ---
#pragma unroll
    for (int mt = 0; mt < 2; mt++) {
#pragma unroll
        for (int half = 0; half < 2; half++) {
            const int rl = wm0 + mt * 16 + g8 + half * 8;
            float cfr[8];
#pragma unroll
            for (int e2 = 0; e2 < 8; e2++) cfr[e2] = coefS[rl * 9 + e2];
            float* orow = out + (size_t)(m0 + rl) * N + n0;
#pragma unroll
            for (int nt = 0; nt < NTN; nt++) {
                const int cl = wn0 + nt * 8 + t4 * 2;
                float v0 = acc[mt][nt][half * 2 + 0];
                float v1 = acc[mt][nt][half * 2 + 1];
#pragma unroll
                for (int e2 = 0; e2 < 8; e2++) {
                    v0 = fmaf(cfr[e2], biasS[e2 * BN + cl], v0);
                    v1 = fmaf(cfr[e2], biasS[e2 * BN + cl + 1], v1);
                }
                if (ELU) { v0 = elu1(v0); v1 = elu1(v1); }
                *(float2*)(orow + cl) = make_float2(v0, v1);
            }
        }
    }
}

// ---------------------------------------------------------------------------

static constexpr int smem_bytes(int BN) {
    return 3 * 128 * 40 * 4 + 3 * 8 * (BN + 4) * 8 + (128 * 9 + 8 * BN) * 4;
}

extern "C" void kernel_launch(void* const* d_in, const int* in_sizes, int n_in,
                              void* d_out, int out_size)
{
    const float* z   = (const float*)d_in[0];
    const float* c   = (const float*)d_in[1];
    const float* w0  = (const float*)d_in[2];
    const float* b0  = (const float*)d_in[3];
    const float* w1  = (const float*)d_in[4];
    const float* b1  = (const float*)d_in[5];
    const float* w2  = (const float*)d_in[6];
    const float* b2  = (const float*)d_in[7];
    const float* gw1 = (const float*)d_in[8];
    const float* gb1 = (const float*)d_in[9];
    const float* gw2 = (const float*)d_in[10];
    const float* gb2 = (const float*)d_in[11];
    const float* gw3 = (const float*)d_in[12];
    const float* gb3 = (const float*)d_in[13];

    float *coef, *h0, *h1;
    uint2 *wp0, *wp1, *wp2;
    cudaGetSymbolAddress((void**)&coef, g_coef);
    cudaGetSymbolAddress((void**)&h0, g_h0);
    cudaGetSymbolAddress((void**)&h1, g_h1);
    cudaGetSymbolAddress((void**)&wp0, g_wp0);
    cudaGetSymbolAddress((void**)&wp1, g_wp1);
    cudaGetSymbolAddress((void**)&wp2, g_wp2);

    cudaFuncSetAttribute(mixed_tc_kernel<512, 1024, 128, true>,
                         cudaFuncAttributeMaxDynamicSharedMemorySize, smem_bytes(128));
    cudaFuncSetAttribute(mixed_tc_kernel<1024, 1024, 128, true>,
                         cudaFuncAttributeMaxDynamicSharedMemorySize, smem_bytes(128));
    cudaFuncSetAttribute(mixed_tc_kernel<1024, 512, 64, false>,
                         cudaFuncAttributeMaxDynamicSharedMemorySize, smem_bytes(64));

    // pack weights to f16x2 fragment-pair layout
    {
        int t0 = 4608 / 4 * 1024;
        int t1 = 8704 / 4 * 1024;
        int t2 = 8704 / 4 * 512;
        pack_kernel<1024><<<(t0 + 255) / 256, 256>>>(w0, wp0, t0);
        pack_kernel<1024><<<(t1 + 255) / 256, 256>>>(w1, wp1, t1);
        pack_kernel<512><<<(t2 + 255) / 256, 256>>>(w2, wp2, t2);
    }

    gate_kernel<<<NB / 8, 128>>>(z, c, gw1, gb1, gw2, gb2, gw3, gb3, coef);

    // layer0: M=4096, K=4608, N=1024
    mixed_tc_kernel<512, 1024, 128, true>
        <<<dim3(1024 / 128, NB / 128), 256, smem_bytes(128)>>>(z, c, wp0, b0, coef, h0);

    // layer1: M=4096, K=8704, N=1024
    mixed_tc_kernel<1024, 1024, 128, true>
        <<<dim3(1024 / 128, NB / 128), 256, smem_bytes(128)>>>(z, h0, wp1, b1, coef, h1);

    // layer2: M=4096, K=8704, N=512
    mixed_tc_kernel<1024, 512, 64, false>
        <<<dim3(512 / 64, NB / 128), 256, smem_bytes(64)>>>(z, h1, wp2, b2, coef, (float*)d_out);
}